// round 13
// baseline (speedup 1.0000x reference)
#include <cuda_runtime.h>
#include <cstdint>

typedef unsigned long long ull;

#define MAXN (1 << 21)
#define LN2F 0.69314718055994530942f

// g_nodes[i] packs {p : lo 32, sum : hi 32} in one 8B word. Final state:
// p == N, hi = full path sum.
__device__ ull g_nodes[MAXN];

__device__ __forceinline__ ull pack_node(unsigned p, float t) {
    return ((ull)__float_as_uint(t) << 32) | (ull)p;
}
__device__ __forceinline__ void st_cg(ull* a, ull v) {
    asm volatile("st.relaxed.gpu.b64 [%0], %1;" :: "l"(a), "l"(v) : "memory");
}

// MUFU-lean scoring: 9 lg2 (ln2 folded into weights), lshape = exp2(0.5(L7-L6))
// reusing the logs, sigmoid = ex2 + rcp, sincos.
__device__ __forceinline__ float node_score(const float* f, const float* w, float b)
{
    float z = b;
    z += w[0] * f[0] + w[1] * f[1] + w[2] * f[2] + w[3] * f[3] + w[4] * f[4];

    float L[9];
    #pragma unroll
    for (int j = 0; j < 9; j++)
        L[j] = __log2f(fabsf(f[6 + j]) + 1e-10f);
    #pragma unroll
    for (int j = 0; j < 9; j++)
        z += (w[5 + j] * LN2F) * L[j];

    z += w[14] * exp2f(0.5f * (L[1] - L[0]));

    float sn, cs;
    __sincosf(f[5], &sn, &cs);
    z += w[15] * cs + w[16] * sn;

    return 1.0f / (1.0f + __expf(-z));
}

__device__ __forceinline__ void phase1_body(float* s_attr,
                                            const float* __restrict__ diff,
                                            const float* __restrict__ attr,
                                            const float* __restrict__ weight,
                                            const float* __restrict__ bias,
                                            const int*   __restrict__ parent,
                                            int base, int p1_end, int N)
{
    const int tid = threadIdx.x;
    const int i   = base + tid;

    float d_pref = 0.0f;
    int   q_pref = 0;
    if (i < p1_end) { d_pref = __ldcs(diff + i); q_pref = __ldcs(parent + i); }

    if (base + 256 <= p1_end) {
        const float4* src = (const float4*)(attr + (size_t)base * 15);
        float4* dst = (float4*)s_attr;
        dst[tid]       = __ldcs(src + tid);
        dst[tid + 256] = __ldcs(src + tid + 256);
        dst[tid + 512] = __ldcs(src + tid + 512);
        if (tid < 192) dst[tid + 768] = __ldcs(src + tid + 768);
    } else {
        const int rem = (p1_end - base) * 15;
        for (int k = tid; k < rem; k += 256)
            s_attr[k] = __ldcs(attr + (size_t)base * 15 + k);
    }
    __syncthreads();

    if (i >= p1_end) return;

    float w[17];
    #pragma unroll
    for (int k = 0; k < 17; k++) w[k] = __ldg(weight + k);
    const float b = __ldg(bias);

    const float t = d_pref * node_score(s_attr + tid * 15, w, b);
    g_nodes[i] = pack_node((q_pref < 0) ? (unsigned)N : (unsigned)q_pref, t);
}

__device__ __forceinline__ void resolve_body(int i, int rs_end, int N)
{
    if (i >= rs_end) return;
    const unsigned Nu = (unsigned)N;

    ull cur = __ldg(&g_nodes[i]);
    unsigned p = (unsigned)cur;
    float    t = __uint_as_float((unsigned)(cur >> 32));

    while (p != Nu) {
        const ull m = __ldg(&g_nodes[p]);
        t += __uint_as_float((unsigned)(m >> 32));
        p = (unsigned)m;
    }
    st_cg(&g_nodes[i], pack_node(Nu, t));
}

// ---------------------------------------------------------------------------
// Combined phase1+resolve kernel (Bresenham-interleaved roles). Phase1 is
// MUFU/DRAM-bound, resolve is l1tex/latency-bound -> resolve rides free.
// ---------------------------------------------------------------------------
__global__ __launch_bounds__(256)
void combined_kernel(const float* __restrict__ diff,
                     const float* __restrict__ attr,
                     const float* __restrict__ weight,
                     const float* __restrict__ bias,
                     const int*   __restrict__ parent,
                     int N,
                     int p1_base, int p1_end,
                     int rs_start, int rs_end,
                     int pb, int rb)
{
    __shared__ float s_attr[256 * 15];
    const int bid   = (int)blockIdx.x;
    const int total = pb + rb;

    const long long rb64 = rb;
    const int r_before = (int)((rb64 * bid) / total);
    const int r_after  = (int)((rb64 * (bid + 1)) / total);

    if (r_after > r_before) {
        resolve_body(rs_start + r_before * 256 + (int)threadIdx.x, rs_end, N);
    } else {
        const int p_idx = bid - r_before;
        phase1_body(s_attr, diff, attr, weight, bias, parent,
                    p1_base + p_idx * 256, p1_end, N);
    }
}

// ---------------------------------------------------------------------------
// Dual-role final kernel with Bresenham-INTERLEAVED roles: rb resolve blocks
// spread uniformly among gb gather blocks, so resolve's latency-bound
// wavefronts ride inside gather's l1tex saturation instead of serializing
// ahead of it. Gather lanes that reach a still-unresolved node chase it
// themselves (all ancestors < rs_start are final; expected 1.39 hops; chased
// sums are bit-identical to resolver sums since path order is fixed) and
// publish the final state for later touchers.
// ---------------------------------------------------------------------------
__global__ __launch_bounds__(256)
void gather_resolve_kernel(const int* __restrict__ pn, float* __restrict__ out,
                           int M, int N, int rs_start, int rb, int gb)
{
    const unsigned Nu = (unsigned)N;
    const int bid = (int)blockIdx.x;
    const int tid = (int)threadIdx.x;
    const int total = rb + gb;

    const long long rb64 = rb;
    const int r_before = (int)((rb64 * bid) / total);
    const int r_after  = (int)((rb64 * (bid + 1)) / total);

    if (r_after > r_before) {
        // resolve role
        resolve_body(rs_start + r_before * 256 + tid, N, N);
        return;
    }

    // gather role
    const int j  = (bid - r_before) * 256 + tid;
    const int i4 = j * 4;

    if (i4 + 3 < M) {
        const int4 pv = __ldcs((const int4*)pn + j);
        int idx[4] = {pv.x, pv.y, pv.z, pv.w};

        ull m[4];
        #pragma unroll
        for (int k = 0; k < 4; k++) m[k] = __ldg(&g_nodes[idx[k]]);

        float o[4];
        #pragma unroll
        for (int k = 0; k < 4; k++) {
            unsigned p = (unsigned)m[k];
            float    s = __uint_as_float((unsigned)(m[k] >> 32));
            if (p != Nu) {                       // only early in the kernel
                do {
                    const ull mm = __ldg(&g_nodes[p]);
                    s += __uint_as_float((unsigned)(mm >> 32));
                    p = (unsigned)mm;
                } while (p != Nu);
                st_cg(&g_nodes[idx[k]], pack_node(Nu, s));  // help later touchers
            }
            o[k] = s;
        }

        float4 ov = {o[0], o[1], o[2], o[3]};
        __stcs((float4*)out + j, ov);
    } else {
        for (int k = i4; k < M; k++) {
            const int idx = __ldcs(pn + k);
            ull cur = __ldg(&g_nodes[idx]);
            unsigned p = (unsigned)cur;
            float    s = __uint_as_float((unsigned)(cur >> 32));
            while (p != Nu) {
                const ull mm = __ldg(&g_nodes[p]);
                s += __uint_as_float((unsigned)(mm >> 32));
                p = (unsigned)mm;
            }
            out[k] = s;
        }
    }
}

static inline int round256(int x) { return ((x + 255) / 256) * 256; }

extern "C" void kernel_launch(void* const* d_in, const int* in_sizes, int n_in,
                              void* d_out, int out_size)
{
    const float* diff   = (const float*)d_in[0];
    const float* attr   = (const float*)d_in[1];
    const float* weight = (const float*)d_in[2];
    const float* bias   = (const float*)d_in[3];
    const int*   parent = (const int*)d_in[4];
    const int*   pn     = (const int*)d_in[5];
    float*       out    = (float*)d_out;

    const int N = in_sizes[0];
    const int M = out_size;

    int c1 = round256(N >> 4); if (c1 > N) c1 = N;
    int c2 = round256(N >> 1); if (c2 > N) c2 = N; if (c2 < c1) c2 = c1;

    // K1: phase1 [0, c1)
    {
        const int pb = (c1 + 255) / 256;
        if (pb > 0)
            combined_kernel<<<pb, 256>>>(diff, attr, weight, bias, parent, N,
                                         0, c1, 0, 0, pb, 0);
    }
    // K2: phase1 [c1, c2) + resolve [0, c1)
    {
        const int pb = (c2 - c1 + 255) / 256;
        const int rb = (c1 + 255) / 256;
        if (pb + rb > 0)
            combined_kernel<<<pb + rb, 256>>>(diff, attr, weight, bias, parent, N,
                                              c1, c2, 0, c1, pb, rb);
    }
    // K3: phase1 [c2, N) + resolve [c1, c2)
    {
        const int pb = (N - c2 + 255) / 256;
        const int rb = (c2 - c1 + 255) / 256;
        if (pb + rb > 0)
            combined_kernel<<<pb + rb, 256>>>(diff, attr, weight, bias, parent, N,
                                              c2, N, c1, c2, pb, rb);
    }
    // K4: resolve [c2, N) interleaved into the gather.
    {
        const int rb = (N - c2 + 255) / 256;
        const int gb = ((M + 3) / 4 + 255) / 256;
        gather_resolve_kernel<<<rb + gb, 256>>>(pn, out, M, N, c2, rb, gb);
    }
}

// round 14
// speedup vs baseline: 1.2020x; 1.2020x over previous
#include <cuda_runtime.h>
#include <cstdint>

typedef unsigned long long ull;

#define MAXN (1 << 21)
#define LN2F 0.69314718055994530942f

// g_nodes[i] packs {p : lo 32, sum : hi 32} in one 8B word. Final state:
// p == N, hi = full path sum.
__device__ ull g_nodes[MAXN];

__device__ __forceinline__ ull pack_node(unsigned p, float t) {
    return ((ull)__float_as_uint(t) << 32) | (ull)p;
}
__device__ __forceinline__ void st_cg(ull* a, ull v) {
    asm volatile("st.relaxed.gpu.b64 [%0], %1;" :: "l"(a), "l"(v) : "memory");
}

// MUFU-lean scoring: 9 lg2 (ln2 folded into weights), lshape = exp2(0.5(L7-L6))
// reusing the logs, sigmoid = ex2 + rcp, sincos.
__device__ __forceinline__ float node_score(const float* f, const float* w, float b)
{
    float z = b;
    z += w[0] * f[0] + w[1] * f[1] + w[2] * f[2] + w[3] * f[3] + w[4] * f[4];

    float L[9];
    #pragma unroll
    for (int j = 0; j < 9; j++)
        L[j] = __log2f(fabsf(f[6 + j]) + 1e-10f);
    #pragma unroll
    for (int j = 0; j < 9; j++)
        z += (w[5 + j] * LN2F) * L[j];

    z += w[14] * exp2f(0.5f * (L[1] - L[0]));

    float sn, cs;
    __sincosf(f[5], &sn, &cs);
    z += w[15] * cs + w[16] * sn;

    return 1.0f / (1.0f + __expf(-z));
}

__device__ __forceinline__ void phase1_body(float* s_attr,
                                            const float* __restrict__ diff,
                                            const float* __restrict__ attr,
                                            const float* __restrict__ weight,
                                            const float* __restrict__ bias,
                                            const int*   __restrict__ parent,
                                            int base, int p1_end, int N)
{
    const int tid = threadIdx.x;
    const int i   = base + tid;

    float d_pref = 0.0f;
    int   q_pref = 0;
    if (i < p1_end) { d_pref = __ldcs(diff + i); q_pref = __ldcs(parent + i); }

    if (base + 256 <= p1_end) {
        const float4* src = (const float4*)(attr + (size_t)base * 15);
        float4* dst = (float4*)s_attr;
        dst[tid]       = __ldcs(src + tid);
        dst[tid + 256] = __ldcs(src + tid + 256);
        dst[tid + 512] = __ldcs(src + tid + 512);
        if (tid < 192) dst[tid + 768] = __ldcs(src + tid + 768);
    } else {
        const int rem = (p1_end - base) * 15;
        for (int k = tid; k < rem; k += 256)
            s_attr[k] = __ldcs(attr + (size_t)base * 15 + k);
    }
    __syncthreads();

    if (i >= p1_end) return;

    float w[17];
    #pragma unroll
    for (int k = 0; k < 17; k++) w[k] = __ldg(weight + k);
    const float b = __ldg(bias);

    const float t = d_pref * node_score(s_attr + tid * 15, w, b);
    g_nodes[i] = pack_node((q_pref < 0) ? (unsigned)N : (unsigned)q_pref, t);
}

__device__ __forceinline__ void resolve_body(int i, int rs_end, int N)
{
    if (i >= rs_end) return;
    const unsigned Nu = (unsigned)N;

    ull cur = __ldg(&g_nodes[i]);
    unsigned p = (unsigned)cur;
    float    t = __uint_as_float((unsigned)(cur >> 32));

    while (p != Nu) {
        const ull m = __ldg(&g_nodes[p]);
        t += __uint_as_float((unsigned)(m >> 32));
        p = (unsigned)m;
    }
    st_cg(&g_nodes[i], pack_node(Nu, t));
}

// ILP-2 resolve: two independent chains per thread, interleaved to double
// outstanding dependent loads during K4's latency-bound resolve head.
__device__ __forceinline__ void resolve_body2(int i0, int rs_end, int N)
{
    const unsigned Nu = (unsigned)N;
    const int i1 = i0 + 256;

    unsigned pa = Nu, pb = Nu;
    float    sa = 0.f, sb = 0.f;
    if (i0 < rs_end) {
        const ull c = __ldg(&g_nodes[i0]);
        pa = (unsigned)c; sa = __uint_as_float((unsigned)(c >> 32));
    }
    if (i1 < rs_end) {
        const ull c = __ldg(&g_nodes[i1]);
        pb = (unsigned)c; sb = __uint_as_float((unsigned)(c >> 32));
    }

    while (pa != Nu || pb != Nu) {
        if (pa != Nu) {
            const ull m = __ldg(&g_nodes[pa]);
            sa += __uint_as_float((unsigned)(m >> 32));
            pa = (unsigned)m;
        }
        if (pb != Nu) {
            const ull m = __ldg(&g_nodes[pb]);
            sb += __uint_as_float((unsigned)(m >> 32));
            pb = (unsigned)m;
        }
    }

    if (i0 < rs_end) st_cg(&g_nodes[i0], pack_node(Nu, sa));
    if (i1 < rs_end) st_cg(&g_nodes[i1], pack_node(Nu, sb));
}

// ---------------------------------------------------------------------------
// Combined phase1+resolve kernel (Bresenham-interleaved roles). Phase1 is
// MUFU/DRAM-bound, resolve is l1tex/latency-bound -> resolve rides free.
// ---------------------------------------------------------------------------
__global__ __launch_bounds__(256)
void combined_kernel(const float* __restrict__ diff,
                     const float* __restrict__ attr,
                     const float* __restrict__ weight,
                     const float* __restrict__ bias,
                     const int*   __restrict__ parent,
                     int N,
                     int p1_base, int p1_end,
                     int rs_start, int rs_end,
                     int pb, int rb)
{
    __shared__ float s_attr[256 * 15];
    const int bid   = (int)blockIdx.x;
    const int total = pb + rb;

    const long long rb64 = rb;
    const int r_before = (int)((rb64 * bid) / total);
    const int r_after  = (int)((rb64 * (bid + 1)) / total);

    if (r_after > r_before) {
        resolve_body(rs_start + r_before * 256 + (int)threadIdx.x, rs_end, N);
    } else {
        const int p_idx = bid - r_before;
        phase1_body(s_attr, diff, attr, weight, bias, parent,
                    p1_base + p_idx * 256, p1_end, N);
    }
}

// ---------------------------------------------------------------------------
// Dual-role final kernel: blocks [0, rb) resolve the last slab [rs_start, N)
// FIRST (resolve-first ordering is load-bearing: it keeps the gather's
// chase-on-demand fallback rare) with ILP-2 so the resolve head is ~1.5
// waves instead of ~3.5. Remaining blocks gather 4 px/thread; lanes hitting
// a still-unresolved node chase it themselves (ancestors < rs_start are
// final; chased sums are bit-identical since path order is fixed) and
// publish the final state for later touchers.
// ---------------------------------------------------------------------------
__global__ __launch_bounds__(256)
void gather_resolve_kernel(const int* __restrict__ pn, float* __restrict__ out,
                           int M, int N, int rs_start, int rb)
{
    const unsigned Nu = (unsigned)N;
    const int bid = (int)blockIdx.x;
    const int tid = (int)threadIdx.x;

    if (bid < rb) {
        resolve_body2(rs_start + bid * 512 + tid, N, N);
        return;
    }

    const int j  = (bid - rb) * 256 + tid;
    const int i4 = j * 4;

    if (i4 + 3 < M) {
        const int4 pv = __ldcs((const int4*)pn + j);
        int idx[4] = {pv.x, pv.y, pv.z, pv.w};

        ull m[4];
        #pragma unroll
        for (int k = 0; k < 4; k++) m[k] = __ldg(&g_nodes[idx[k]]);

        float o[4];
        #pragma unroll
        for (int k = 0; k < 4; k++) {
            unsigned p = (unsigned)m[k];
            float    s = __uint_as_float((unsigned)(m[k] >> 32));
            if (p != Nu) {                       // rare after the resolve head
                do {
                    const ull mm = __ldg(&g_nodes[p]);
                    s += __uint_as_float((unsigned)(mm >> 32));
                    p = (unsigned)mm;
                } while (p != Nu);
                st_cg(&g_nodes[idx[k]], pack_node(Nu, s));  // help later touchers
            }
            o[k] = s;
        }

        float4 ov = {o[0], o[1], o[2], o[3]};
        __stcs((float4*)out + j, ov);
    } else {
        for (int k = i4; k < M; k++) {
            const int idx = __ldcs(pn + k);
            ull cur = __ldg(&g_nodes[idx]);
            unsigned p = (unsigned)cur;
            float    s = __uint_as_float((unsigned)(cur >> 32));
            while (p != Nu) {
                const ull mm = __ldg(&g_nodes[p]);
                s += __uint_as_float((unsigned)(mm >> 32));
                p = (unsigned)mm;
            }
            out[k] = s;
        }
    }
}

static inline int round256(int x) { return ((x + 255) / 256) * 256; }

extern "C" void kernel_launch(void* const* d_in, const int* in_sizes, int n_in,
                              void* d_out, int out_size)
{
    const float* diff   = (const float*)d_in[0];
    const float* attr   = (const float*)d_in[1];
    const float* weight = (const float*)d_in[2];
    const float* bias   = (const float*)d_in[3];
    const int*   parent = (const int*)d_in[4];
    const int*   pn     = (const int*)d_in[5];
    float*       out    = (float*)d_out;

    const int N = in_sizes[0];
    const int M = out_size;

    // c1 ~ N/16; c2 ~ 9N/16 (shifted up from N/2 to move ~N/16 of resolve
    // work from K4's unhidden head into K3's hidden slot).
    int c1 = round256(N >> 4); if (c1 > N) c1 = N;
    long long c2ll = (9LL * N) >> 4;
    int c2 = round256((int)c2ll); if (c2 > N) c2 = N; if (c2 < c1) c2 = c1;

    // K1: phase1 [0, c1)
    {
        const int pb = (c1 + 255) / 256;
        if (pb > 0)
            combined_kernel<<<pb, 256>>>(diff, attr, weight, bias, parent, N,
                                         0, c1, 0, 0, pb, 0);
    }
    // K2: phase1 [c1, c2) + resolve [0, c1)
    {
        const int pb = (c2 - c1 + 255) / 256;
        const int rb = (c1 + 255) / 256;
        if (pb + rb > 0)
            combined_kernel<<<pb + rb, 256>>>(diff, attr, weight, bias, parent, N,
                                              c1, c2, 0, c1, pb, rb);
    }
    // K3: phase1 [c2, N) + resolve [c1, c2)
    {
        const int pb = (N - c2 + 255) / 256;
        const int rb = (c2 - c1 + 255) / 256;
        if (pb + rb > 0)
            combined_kernel<<<pb + rb, 256>>>(diff, attr, weight, bias, parent, N,
                                              c2, N, c1, c2, pb, rb);
    }
    // K4: resolve [c2, N) (ILP-2, resolve-first) fused into the gather.
    {
        const int rb = (N - c2 + 511) / 512;
        const int gb = ((M + 3) / 4 + 255) / 256;
        gather_resolve_kernel<<<rb + gb, 256>>>(pn, out, M, N, c2, rb);
    }
}